// round 14
// baseline (speedup 1.0000x reference)
#include <cuda_runtime.h>
#include <cstdint>

#define B_ 16
#define T_ 2048
#define D_ 256
#define C_ 8
#define TILE 32
#define TPB 2                      // tiles per block
#define TCHUNK (TILE * TPB)        // 64 tokens per block
#define NCHUNKS (T_ / TCHUNK)      // 32
#define NBLOCKS (B_ * NCHUNKS)     // 512
#define NTHREADS 128

typedef unsigned long long ull;
union f4u { float4 v; ull u[2]; };

// scratch: per-block partial aggregates, layout [block][d][c]
__device__ float g_scratch[NBLOCKS * 2048];
__device__ float g_asum[NBLOCKS * C_];
__device__ unsigned int g_count[B_];   // zero-init; reset by last block each launch

__device__ __forceinline__ ull ffma2(ull a, ull b, ull c) {
    ull d;
    asm("fma.rn.f32x2 %0, %1, %2, %3;" : "=l"(d) : "l"(a), "l"(b), "l"(c));
    return d;
}
__device__ __forceinline__ float2 upk(ull v) {
    float2 r;
    asm("mov.b64 {%0, %1}, %2;" : "=f"(r.x), "=f"(r.y) : "l"(v));
    return r;
}
__device__ __forceinline__ ull pk2(float lo, float hi) {
    ull r;
    asm("mov.b64 %0, {%1, %2};" : "=l"(r) : "f"(lo), "f"(hi));
    return r;
}
__device__ __forceinline__ void cp16(uint32_t saddr, const void* g) {
    asm volatile("cp.async.cg.shared.global [%0], [%1], 16;" :: "r"(saddr), "l"(g));
}
#define CP_COMMIT() asm volatile("cp.async.commit_group;")
#define CP_WAIT0()  asm volatile("cp.async.wait_group 0;")

__global__ void __launch_bounds__(NTHREADS, 5) lde_main_kernel(
    const float* __restrict__ x,        // (B,T,D)
    const float* __restrict__ centers,  // (C,D)
    const float* __restrict__ scale,    // (C,)
    float* __restrict__ out)            // (B, C*D)
{
    __shared__ float4 xbuf[TILE * 64];   // 32 KB, swizzled slot = d4 ^ t
    __shared__ float4 ct[64 * C_];       // 8 KB: [d4][c]
    __shared__ float  logit[TILE * 9];   // per token: 8 dots + xsq
    __shared__ float  a_s[TILE * C_];    // softmax weights
    __shared__ float  asum_s[C_];
    __shared__ float  csq_s[C_];
    __shared__ float  scl_s[C_];
    __shared__ float  asumtot[C_];
    __shared__ int    is_last;

    const int tid  = threadIdx.x;
    const int w    = tid >> 5;           // 0..3
    const int lane = tid & 31;
    const int b     = blockIdx.x >> 5;        // / NCHUNKS (32)
    const int chunk = blockIdx.x & (NCHUNKS - 1);

    const float4* gx4 = (const float4*)(x + ((size_t)b * T_ + chunk * TCHUNK) * D_);
    const uint32_t xs_base = (uint32_t)__cvta_generic_to_shared(xbuf);

    // ---- issue tile 0 load (32 KB) ----
#pragma unroll
    for (int j = 0; j < 16; j++) {
        int i = tid + j * NTHREADS;
        int t = i >> 6, d4 = i & 63;
        cp16(xs_base + (uint32_t)((t * 64 + (d4 ^ t)) * 16), gx4 + i);
    }
    CP_COMMIT();

    // ---- init (overlaps cp.async flight) ----
    for (int i = tid; i < TILE * 9; i += NTHREADS) logit[i] = 0.0f;
    if (tid < C_) { asum_s[tid] = 0.0f; scl_s[tid] = scale[tid]; }
    for (int i = tid; i < C_ * D_; i += NTHREADS) {
        int c = i >> 8, d = i & 255;
        ((float*)ct)[((d >> 2) * C_ + c) * 4 + (d & 3)] = centers[i];
    }
    {
        float s0 = 0.0f, s1 = 0.0f;
#pragma unroll
        for (int j = 0; j < 8; j++) {
            float v0 = centers[(2 * w) * D_ + lane + 32 * j];
            float v1 = centers[(2 * w + 1) * D_ + lane + 32 * j];
            s0 = fmaf(v0, v0, s0);
            s1 = fmaf(v1, v1, s1);
        }
#pragma unroll
        for (int o = 16; o; o >>= 1) {
            s0 += __shfl_xor_sync(0xffffffffu, s0, o);
            s1 += __shfl_xor_sync(0xffffffffu, s1, o);
        }
        if (lane == 0) { csq_s[2 * w] = s0; csq_s[2 * w + 1] = s1; }
    }

    // phase-B constants and cross-tile accumulators
    const int d4l = tid >> 1;
    const int off = (tid & 1) * 2;
    ull acc2[8];
#pragma unroll
    for (int j = 0; j < 8; j++) acc2[j] = 0ULL;

#pragma unroll
    for (int tile = 0; tile < TPB; tile++) {
        CP_WAIT0();
        __syncthreads();   // tile data + (logit zeroed) ready

        // ---- phase A: lane = token, warp w covers d4 in [16w, 16w+16) ----
        {
            ull red[9];
#pragma unroll
            for (int j = 0; j < 9; j++) red[j] = 0ULL;
#pragma unroll
            for (int i = 0; i < 16; i++) {
                const int d4 = w * 16 + i;
                f4u xv; xv.v = xbuf[lane * 64 + (d4 ^ lane)];
#pragma unroll
                for (int c = 0; c < C_; c++) {
                    f4u cv; cv.v = ct[d4 * C_ + c];
                    red[c] = ffma2(xv.u[0], cv.u[0], ffma2(xv.u[1], cv.u[1], red[c]));
                }
                red[8] = ffma2(xv.u[0], xv.u[0], ffma2(xv.u[1], xv.u[1], red[8]));
            }
#pragma unroll
            for (int j = 0; j < 9; j++) {
                float2 p = upk(red[j]);
                atomicAdd(&logit[lane * 9 + j], p.x + p.y);
            }
        }
        __syncthreads();

        // ---- softmax: thread = (t = tid/4, cluster pair q = tid%4) ----
        {
            const int t  = tid >> 2;
            const int q  = tid & 3;
            const int c0 = 2 * q, c1 = 2 * q + 1;
            const float dot0 = logit[t * 9 + c0];
            const float dot1 = logit[t * 9 + c1];
            const float xsq  = logit[t * 9 + 8];
            logit[t * 9 + c0] = 0.0f;
            logit[t * 9 + c1] = 0.0f;
            if (q == 0) logit[t * 9 + 8] = 0.0f;
            float lg0 = scl_s[c0] * (2.0f * dot0 - xsq - csq_s[c0]);
            float lg1 = scl_s[c1] * (2.0f * dot1 - xsq - csq_s[c1]);
            float m = fmaxf(lg0, lg1);
            m = fmaxf(m, __shfl_xor_sync(0xffffffffu, m, 1));
            m = fmaxf(m, __shfl_xor_sync(0xffffffffu, m, 2));
            const float e0 = __expf(lg0 - m);
            const float e1 = __expf(lg1 - m);
            float sd = e0 + e1;
            sd += __shfl_xor_sync(0xffffffffu, sd, 1);
            sd += __shfl_xor_sync(0xffffffffu, sd, 2);
            const float inv = 1.0f / sd;
            const float a0 = e0 * inv, a1 = e1 * inv;
            *(float2*)&a_s[t * 8 + c0] = make_float2(a0, a1);
            float r0 = a0, r1 = a1;
            r0 += __shfl_xor_sync(0xffffffffu, r0, 4);
            r1 += __shfl_xor_sync(0xffffffffu, r1, 4);
            r0 += __shfl_xor_sync(0xffffffffu, r0, 8);
            r1 += __shfl_xor_sync(0xffffffffu, r1, 8);
            r0 += __shfl_xor_sync(0xffffffffu, r0, 16);
            r1 += __shfl_xor_sync(0xffffffffu, r1, 16);
            if (lane < 4) {
                atomicAdd(&asum_s[c0], r0);
                atomicAdd(&asum_s[c1], r1);
            }
        }
        __syncthreads();

        // ---- phase B: thread owns dims {2*tid, 2*tid+1}, accumulate tile ----
        {
            const float* xbf = (const float*)xbuf;
#pragma unroll 4
            for (int t = 0; t < TILE; t++) {
                const ull xp = *(const ull*)(xbf + (t * 64 + (d4l ^ t)) * 4 + off);
                const float2 xv = upk(xp);
                const ull xd0 = pk2(xv.x, xv.x);
                const ull xd1 = pk2(xv.y, xv.y);
                f4u a0; a0.v = *(const float4*)&a_s[t * 8];
                f4u a1; a1.v = *(const float4*)&a_s[t * 8 + 4];
                acc2[0] = ffma2(a0.u[0], xd0, acc2[0]);
                acc2[1] = ffma2(a0.u[0], xd1, acc2[1]);
                acc2[2] = ffma2(a0.u[1], xd0, acc2[2]);
                acc2[3] = ffma2(a0.u[1], xd1, acc2[3]);
                acc2[4] = ffma2(a1.u[0], xd0, acc2[4]);
                acc2[5] = ffma2(a1.u[0], xd1, acc2[5]);
                acc2[6] = ffma2(a1.u[1], xd0, acc2[6]);
                acc2[7] = ffma2(a1.u[1], xd1, acc2[7]);
            }
        }

        // ---- issue next tile load after xbuf reads complete ----
        if (tile + 1 < TPB) {
            __syncthreads();
            const float4* src = gx4 + (tile + 1) * (TILE * 64);
#pragma unroll
            for (int j = 0; j < 16; j++) {
                int i = tid + j * NTHREADS;
                int t = i >> 6, d4 = i & 63;
                cp16(xs_base + (uint32_t)((t * 64 + (d4 ^ t)) * 16), src + i);
            }
            CP_COMMIT();
        }
    }

    // ---- epilogue: vectorized stores of raw partials ----
    {
        float* sb = g_scratch + (size_t)blockIdx.x * 2048;   // [d][c]
        const int d0 = 2 * tid, d1 = 2 * tid + 1;
        f4u q0, q1, q2, q3;
        q0.u[0] = acc2[0]; q0.u[1] = acc2[2];
        q1.u[0] = acc2[4]; q1.u[1] = acc2[6];
        q2.u[0] = acc2[1]; q2.u[1] = acc2[3];
        q3.u[0] = acc2[5]; q3.u[1] = acc2[7];
        *(float4*)(sb + d0 * 8)     = q0.v;
        *(float4*)(sb + d0 * 8 + 4) = q1.v;
        *(float4*)(sb + d1 * 8)     = q2.v;
        *(float4*)(sb + d1 * 8 + 4) = q3.v;
        if (tid < C_) g_asum[blockIdx.x * C_ + tid] = asum_s[tid];
    }

    // ---- last-block fused reduction for this batch ----
    __syncthreads();
    if (tid == 0) {
        __threadfence();
        unsigned r = atomicAdd(&g_count[b], 1u);
        is_last = (r == NCHUNKS - 1);
    }
    __syncthreads();
    if (is_last) {
        __threadfence();   // order reads after observing all arrivals

        // asum totals for this batch
        if (tid < C_) {
            float s = 0.0f;
#pragma unroll 8
            for (int k = 0; k < NCHUNKS; k++)
                s += g_asum[(b * NCHUNKS + k) * C_ + tid];
            asumtot[tid] = s;
        }
        __syncthreads();

        // thread owns dims {2*tid, 2*tid+1}: sum 32 partials of 4 float4 each
        const float* sb = g_scratch + (size_t)b * NCHUNKS * 2048 + tid * 16;
        float4 s0 = make_float4(0.f,0.f,0.f,0.f), s1 = s0, s2 = s0, s3 = s0;
#pragma unroll 4
        for (int k = 0; k < NCHUNKS; k++) {
            const float* p = sb + (size_t)k * 2048;
            float4 a0 = *(const float4*)(p);
            float4 a1 = *(const float4*)(p + 4);
            float4 a2 = *(const float4*)(p + 8);
            float4 a3 = *(const float4*)(p + 12);
            s0.x += a0.x; s0.y += a0.y; s0.z += a0.z; s0.w += a0.w;
            s1.x += a1.x; s1.y += a1.y; s1.z += a1.z; s1.w += a1.w;
            s2.x += a2.x; s2.y += a2.y; s2.z += a2.z; s2.w += a2.w;
            s3.x += a3.x; s3.y += a3.y; s3.z += a3.z; s3.w += a3.w;
        }

        // write out[b][c][d] = sum - asumtot[c]*centers[c][d]
        const float* ctf = (const float*)ct;
        float* ob = out + b * (C_ * D_);
        const int d0 = 2 * tid, d1 = 2 * tid + 1;
        const float* r0 = (const float*)&s0;   // d0, c0..3
        const float* r1 = (const float*)&s1;   // d0, c4..7
        const float* r2 = (const float*)&s2;   // d1, c0..3
        const float* r3 = (const float*)&s3;   // d1, c4..7
#pragma unroll
        for (int c = 0; c < C_; c++) {
            const float cv0 = ctf[(d4l * C_ + c) * 4 + off];       // centers[c][d0]
            const float cv1 = ctf[(d4l * C_ + c) * 4 + off + 1];   // centers[c][d1]
            const float v0 = (c < 4 ? r0[c] : r1[c - 4]) - asumtot[c] * cv0;
            const float v1 = (c < 4 ? r2[c] : r3[c - 4]) - asumtot[c] * cv1;
            *(float2*)(ob + c * 256 + d0) = make_float2(v0, v1);
        }

        if (tid == 0) g_count[b] = 0;   // reset for next graph replay
    }
}

extern "C" void kernel_launch(void* const* d_in, const int* in_sizes, int n_in,
                              void* d_out, int out_size) {
    const float* x       = (const float*)d_in[0];
    const float* centers = (const float*)d_in[1];
    const float* scale   = (const float*)d_in[2];
    float* out           = (float*)d_out;
    (void)in_sizes; (void)n_in; (void)out_size;

    lde_main_kernel<<<NBLOCKS, NTHREADS>>>(x, centers, scale, out);
}

// round 15
// speedup vs baseline: 1.6050x; 1.6050x over previous
#include <cuda_runtime.h>
#include <cstdint>

#define B_ 16
#define T_ 2048
#define D_ 256
#define C_ 8
#define TILE 32
#define TPB 2                      // tiles per block
#define TCHUNK (TILE * TPB)        // 64 tokens per block
#define NCHUNKS (T_ / TCHUNK)      // 32
#define NBLOCKS (B_ * NCHUNKS)     // 512
#define NTHREADS 128
#define KPART NCHUNKS              // 32 partials per (b,d,c)

typedef unsigned long long ull;
union f4u { float4 v; ull u[2]; };

// scratch: per-block partial aggregates, layout [block][d][c]
__device__ float g_scratch[NBLOCKS * 2048];
__device__ float g_asum[NBLOCKS * C_];

__device__ __forceinline__ ull ffma2(ull a, ull b, ull c) {
    ull d;
    asm("fma.rn.f32x2 %0, %1, %2, %3;" : "=l"(d) : "l"(a), "l"(b), "l"(c));
    return d;
}
__device__ __forceinline__ float2 upk(ull v) {
    float2 r;
    asm("mov.b64 {%0, %1}, %2;" : "=f"(r.x), "=f"(r.y) : "l"(v));
    return r;
}
__device__ __forceinline__ ull pk2(float lo, float hi) {
    ull r;
    asm("mov.b64 %0, {%1, %2};" : "=l"(r) : "f"(lo), "f"(hi));
    return r;
}
__device__ __forceinline__ void cp16(uint32_t saddr, const void* g) {
    asm volatile("cp.async.cg.shared.global [%0], [%1], 16;" :: "r"(saddr), "l"(g));
}
#define CP_COMMIT() asm volatile("cp.async.commit_group;")
#define CP_WAIT0()  asm volatile("cp.async.wait_group 0;")

__global__ void __launch_bounds__(NTHREADS, 5) lde_main_kernel(
    const float* __restrict__ x,        // (B,T,D)
    const float* __restrict__ centers,  // (C,D)
    const float* __restrict__ scale)    // (C,)
{
    __shared__ float4 xbuf[TILE * 64];   // 32 KB, swizzled slot = d4 ^ t
    __shared__ float4 ct[64 * C_];       // 8 KB: [d4][c]
    __shared__ float  logit[TILE * 9];   // per token: 8 dots + xsq
    __shared__ float  a_s[TILE * C_];    // softmax weights
    __shared__ float  asum_s[C_];
    __shared__ float  csq_s[C_];
    __shared__ float  scl_s[C_];

    const int tid  = threadIdx.x;
    const int w    = tid >> 5;           // 0..3
    const int lane = tid & 31;
    const int b     = blockIdx.x >> 5;        // / NCHUNKS (32)
    const int chunk = blockIdx.x & (NCHUNKS - 1);

    const float4* gx4 = (const float4*)(x + ((size_t)b * T_ + chunk * TCHUNK) * D_);
    const uint32_t xs_base = (uint32_t)__cvta_generic_to_shared(xbuf);

    // ---- issue tile 0 load (32 KB) ----
#pragma unroll
    for (int j = 0; j < 16; j++) {
        int i = tid + j * NTHREADS;
        int t = i >> 6, d4 = i & 63;
        cp16(xs_base + (uint32_t)((t * 64 + (d4 ^ t)) * 16), gx4 + i);
    }
    CP_COMMIT();

    // ---- init (overlaps cp.async flight) ----
    for (int i = tid; i < TILE * 9; i += NTHREADS) logit[i] = 0.0f;
    if (tid < C_) { asum_s[tid] = 0.0f; scl_s[tid] = scale[tid]; }
    for (int i = tid; i < C_ * D_; i += NTHREADS) {
        int c = i >> 8, d = i & 255;
        ((float*)ct)[((d >> 2) * C_ + c) * 4 + (d & 3)] = centers[i];
    }
    {
        float s0 = 0.0f, s1 = 0.0f;
#pragma unroll
        for (int j = 0; j < 8; j++) {
            float v0 = centers[(2 * w) * D_ + lane + 32 * j];
            float v1 = centers[(2 * w + 1) * D_ + lane + 32 * j];
            s0 = fmaf(v0, v0, s0);
            s1 = fmaf(v1, v1, s1);
        }
#pragma unroll
        for (int o = 16; o; o >>= 1) {
            s0 += __shfl_xor_sync(0xffffffffu, s0, o);
            s1 += __shfl_xor_sync(0xffffffffu, s1, o);
        }
        if (lane == 0) { csq_s[2 * w] = s0; csq_s[2 * w + 1] = s1; }
    }

    // phase-B constants and cross-tile accumulators
    const int d4l = tid >> 1;
    const int off = (tid & 1) * 2;
    ull acc2[8];
#pragma unroll
    for (int j = 0; j < 8; j++) acc2[j] = 0ULL;

#pragma unroll
    for (int tile = 0; tile < TPB; tile++) {
        CP_WAIT0();
        __syncthreads();   // tile data + (logit zeroed) ready

        // ---- phase A: lane = token, warp w covers d4 in [16w, 16w+16) ----
        {
            ull red[9];
#pragma unroll
            for (int j = 0; j < 9; j++) red[j] = 0ULL;
#pragma unroll
            for (int i = 0; i < 16; i++) {
                const int d4 = w * 16 + i;
                f4u xv; xv.v = xbuf[lane * 64 + (d4 ^ lane)];
#pragma unroll
                for (int c = 0; c < C_; c++) {
                    f4u cv; cv.v = ct[d4 * C_ + c];
                    red[c] = ffma2(xv.u[0], cv.u[0], ffma2(xv.u[1], cv.u[1], red[c]));
                }
                red[8] = ffma2(xv.u[0], xv.u[0], ffma2(xv.u[1], xv.u[1], red[8]));
            }
#pragma unroll
            for (int j = 0; j < 9; j++) {
                float2 p = upk(red[j]);
                atomicAdd(&logit[lane * 9 + j], p.x + p.y);
            }
        }
        __syncthreads();

        // ---- softmax: thread = (t = tid/4, cluster pair q = tid%4) ----
        {
            const int t  = tid >> 2;
            const int q  = tid & 3;
            const int c0 = 2 * q, c1 = 2 * q + 1;
            const float dot0 = logit[t * 9 + c0];
            const float dot1 = logit[t * 9 + c1];
            const float xsq  = logit[t * 9 + 8];
            logit[t * 9 + c0] = 0.0f;
            logit[t * 9 + c1] = 0.0f;
            if (q == 0) logit[t * 9 + 8] = 0.0f;
            float lg0 = scl_s[c0] * (2.0f * dot0 - xsq - csq_s[c0]);
            float lg1 = scl_s[c1] * (2.0f * dot1 - xsq - csq_s[c1]);
            float m = fmaxf(lg0, lg1);
            m = fmaxf(m, __shfl_xor_sync(0xffffffffu, m, 1));
            m = fmaxf(m, __shfl_xor_sync(0xffffffffu, m, 2));
            const float e0 = __expf(lg0 - m);
            const float e1 = __expf(lg1 - m);
            float sd = e0 + e1;
            sd += __shfl_xor_sync(0xffffffffu, sd, 1);
            sd += __shfl_xor_sync(0xffffffffu, sd, 2);
            const float inv = 1.0f / sd;
            const float a0 = e0 * inv, a1 = e1 * inv;
            *(float2*)&a_s[t * 8 + c0] = make_float2(a0, a1);
            float r0 = a0, r1 = a1;
            r0 += __shfl_xor_sync(0xffffffffu, r0, 4);
            r1 += __shfl_xor_sync(0xffffffffu, r1, 4);
            r0 += __shfl_xor_sync(0xffffffffu, r0, 8);
            r1 += __shfl_xor_sync(0xffffffffu, r1, 8);
            r0 += __shfl_xor_sync(0xffffffffu, r0, 16);
            r1 += __shfl_xor_sync(0xffffffffu, r1, 16);
            if (lane < 4) {
                atomicAdd(&asum_s[c0], r0);
                atomicAdd(&asum_s[c1], r1);
            }
        }
        __syncthreads();

        // ---- phase B: thread owns dims {2*tid, 2*tid+1}, accumulate tile ----
        {
            const float* xbf = (const float*)xbuf;
#pragma unroll 4
            for (int t = 0; t < TILE; t++) {
                const ull xp = *(const ull*)(xbf + (t * 64 + (d4l ^ t)) * 4 + off);
                const float2 xv = upk(xp);
                const ull xd0 = pk2(xv.x, xv.x);
                const ull xd1 = pk2(xv.y, xv.y);
                f4u a0; a0.v = *(const float4*)&a_s[t * 8];
                f4u a1; a1.v = *(const float4*)&a_s[t * 8 + 4];
                acc2[0] = ffma2(a0.u[0], xd0, acc2[0]);
                acc2[1] = ffma2(a0.u[0], xd1, acc2[1]);
                acc2[2] = ffma2(a0.u[1], xd0, acc2[2]);
                acc2[3] = ffma2(a0.u[1], xd1, acc2[3]);
                acc2[4] = ffma2(a1.u[0], xd0, acc2[4]);
                acc2[5] = ffma2(a1.u[0], xd1, acc2[5]);
                acc2[6] = ffma2(a1.u[1], xd0, acc2[6]);
                acc2[7] = ffma2(a1.u[1], xd1, acc2[7]);
            }
        }

        // ---- issue next tile load after xbuf reads complete ----
        if (tile + 1 < TPB) {
            __syncthreads();
            const float4* src = gx4 + (tile + 1) * (TILE * 64);
#pragma unroll
            for (int j = 0; j < 16; j++) {
                int i = tid + j * NTHREADS;
                int t = i >> 6, d4 = i & 63;
                cp16(xs_base + (uint32_t)((t * 64 + (d4 ^ t)) * 16), src + i);
            }
            CP_COMMIT();
        }
    }

    // ---- epilogue: vectorized stores of raw partials ----
    {
        float* sb = g_scratch + (size_t)blockIdx.x * 2048;   // [d][c]
        const int d0 = 2 * tid, d1 = 2 * tid + 1;
        f4u q0, q1, q2, q3;
        q0.u[0] = acc2[0]; q0.u[1] = acc2[2];
        q1.u[0] = acc2[4]; q1.u[1] = acc2[6];
        q2.u[0] = acc2[1]; q2.u[1] = acc2[3];
        q3.u[0] = acc2[5]; q3.u[1] = acc2[7];
        *(float4*)(sb + d0 * 8)     = q0.v;
        *(float4*)(sb + d0 * 8 + 4) = q1.v;
        *(float4*)(sb + d1 * 8)     = q2.v;
        *(float4*)(sb + d1 * 8 + 4) = q3.v;
        if (tid < C_) g_asum[blockIdx.x * C_ + tid] = asum_s[tid];
    }
}

// stage 2 (PDL): launched with programmatic stream serialization; ramp overlaps
// stage-1 tail; cudaGridDependencySynchronize gates all data reads.
__global__ void __launch_bounds__(256) lde_reduce_kernel(
    const float* __restrict__ centers,
    float* __restrict__ out)
{
    const int b    = blockIdx.x;          // 16
    const int dg   = blockIdx.y;          // 16 groups of 16 d-values
    const int tid  = threadIdx.x;
    const int f    = tid & 31;            // float4 index within 128-float group
    const int kseg = tid >> 5;            // 0..7 (4 k per segment)

    __shared__ float4 red[8][32];
    __shared__ float  asred[KPART][8];
    __shared__ float  asumtot[C_];

    // address setup happens pre-sync (overlapped with stage 1)
    const float4* base = (const float4*)g_scratch
                       + ((size_t)(b * KPART + kseg * 4)) * 512 + dg * 32 + f;

    cudaGridDependencySynchronize();   // wait for stage-1 grid + visibility

    float4 acc = make_float4(0.f, 0.f, 0.f, 0.f);
#pragma unroll
    for (int k = 0; k < 4; k++) {
        float4 p = base[k * 512];
        acc.x += p.x; acc.y += p.y; acc.z += p.z; acc.w += p.w;
    }
    red[kseg][f] = acc;

    if (tid < KPART) {
        const float4* ap = (const float4*)&g_asum[(b * KPART + tid) * C_];
        float4 a0 = ap[0], a1 = ap[1];
        asred[tid][0] = a0.x; asred[tid][1] = a0.y;
        asred[tid][2] = a0.z; asred[tid][3] = a0.w;
        asred[tid][4] = a1.x; asred[tid][5] = a1.y;
        asred[tid][6] = a1.z; asred[tid][7] = a1.w;
    }
    __syncthreads();

    if (tid < C_) {
        float s = 0.0f;
#pragma unroll
        for (int k = 0; k < KPART; k++) s += asred[k][tid];
        asumtot[tid] = s;
    }
    __syncthreads();

    if (tid < 128) {
        const int c  = tid >> 4;
        const int dl = tid & 15;
        const int fi = dl * 8 + c;
        float s = 0.0f;
#pragma unroll
        for (int seg = 0; seg < 8; seg++)
            s += ((const float*)&red[seg][fi >> 2])[fi & 3];
        const int d = dg * 16 + dl;
        out[b * (C_ * D_) + c * 256 + d] = s - asumtot[c] * centers[c * 256 + d];
    }
}

extern "C" void kernel_launch(void* const* d_in, const int* in_sizes, int n_in,
                              void* d_out, int out_size) {
    const float* x       = (const float*)d_in[0];
    const float* centers = (const float*)d_in[1];
    const float* scale   = (const float*)d_in[2];
    float* out           = (float*)d_out;
    (void)in_sizes; (void)n_in; (void)out_size;

    lde_main_kernel<<<NBLOCKS, NTHREADS>>>(x, centers, scale);

    // stage 2 with programmatic dependent launch (overlap ramp with stage-1 tail)
    cudaLaunchConfig_t cfg = {};
    cfg.gridDim  = dim3(B_, 16);
    cfg.blockDim = dim3(256);
    cfg.dynamicSmemBytes = 0;
    cfg.stream = (cudaStream_t)0;   // legacy default stream (capture target)
    cudaLaunchAttribute attrs[1];
    attrs[0].id = cudaLaunchAttributeProgrammaticStreamSerialization;
    attrs[0].val.programmaticStreamSerializationAllowed = 1;
    cfg.attrs = attrs;
    cfg.numAttrs = 1;
    cudaLaunchKernelEx(&cfg, lde_reduce_kernel, centers, out);
}